// round 8
// baseline (speedup 1.0000x reference)
#include <cuda_runtime.h>
#include <cuda_bf16.h>

#define NUM_CHIPS 4
#define N_EXPERTS 32
#define TOP_K 4
#define SEQ 1024
#define HIDDEN 2048
#define MAX_TOK 1024
#define META_LEN 8
#define NPC (SEQ * TOP_K)            /* 4096 assignments per chip  */
#define NA (NUM_CHIPS * NPC)         /* 16384 total assignments    */
#define NROWS (N_EXPERTS * MAX_TOK)  /* 32768 output rows          */
#define EPC 8                        /* experts per chip block      */
#define ROWS_PER_BLOCK (EPC * MAX_TOK)   /* 8192 tail rows / block  */

#define V4_PER_ROW (HIDDEN / 4)      /* 512 float4 per row  */
#define COPY_THREADS 128             /* one block per row; 4 float4/thread */

/* scratch — no allocations allowed */
__device__ int g_counts[NUM_CHIPS * N_EXPERTS];
__device__ int g_srcrow[NROWS];      /* row -> source token row index, or -1 */
__device__ unsigned g_arrived;       /* monotonic cross-launch arrival ctr   */

/* ------------------------------------------------------------------ */
/* Fused plan kernel: 4 blocks (one per chip), 1024 threads.
   Phase A: stable within-chip rank via warp intrinsics (as before).
   Sync  : 4-block handshake on a monotonic counter — each launch adds
           exactly 4, so target=(old&~3)+4 is replay-deterministic.
   Phase B: write srcrow + filled-row metadata straight from registers.
   Phase C: tail rows of this chip's 8 experts -> -1 metadata.          */
__global__ void __launch_bounds__(1024) k_plan(const int* __restrict__ indices,
                                               const float* __restrict__ wts,
                                               float* __restrict__ meta,
                                               float* __restrict__ out_cnt) {
    __shared__ int wcount[32 * 33];   /* [warp][expert], 33-padded */
    __shared__ int woff[32 * 33];
    __shared__ int s_choff[N_EXPERTS];   /* cross-chip offset for my chip */
    __shared__ int s_tot[EPC];           /* totals for my 8 experts       */
    const int c = blockIdx.x;
    const int tid = threadIdx.x, w = tid >> 5, lane = tid & 31;

    for (int i = tid; i < 32 * 33; i += 1024) wcount[i] = 0;
    __syncthreads();

    /* ---- Phase A: within-chip stable rank ---- */
    int er[4], lr[4];
#pragma unroll
    for (int r = 0; r < 4; r++) {
        const int j = w * 128 + r * 32 + lane;          /* coalesced */
        const int e = indices[c * NPC + j];
        const unsigned mask = __match_any_sync(0xffffffffu, e);
        const int leader = __ffs(mask) - 1;
        const int prefix = __popc(mask & ((1u << lane) - 1u));
        int base = 0;
        if (lane == leader) base = atomicAdd(&wcount[w * 33 + e], __popc(mask));
        base = __shfl_sync(0xffffffffu, base, leader);
        er[r] = e; lr[r] = base + prefix;
    }
    __syncthreads();

    /* warp e scans wcount[*][e] across the 32 warps (lane = warp idx) */
    {
        const int e = w;
        const int val = wcount[lane * 33 + e];
        int incl = val;
#pragma unroll
        for (int d = 1; d < 32; d <<= 1) {
            int n = __shfl_up_sync(0xffffffffu, incl, d);
            if (lane >= d) incl += n;
        }
        woff[lane * 33 + e] = incl - val;
        if (lane == 31) g_counts[c * N_EXPERTS + e] = incl;
    }
    __syncthreads();

    /* ---- cross-block handshake (graph-replay-safe, no reset) ---- */
    if (tid == 0) {
        __threadfence();                       /* publish g_counts      */
        const unsigned old = atomicAdd(&g_arrived, 1u);
        const unsigned target = (old & ~3u) + 4u;
        while (*(volatile unsigned*)&g_arrived < target) {}
        __threadfence();                       /* acquire others' counts */
    }
    __syncthreads();

    /* cross-chip exclusive offsets + my experts' totals into smem */
    if (tid < N_EXPERTS) {
        int off = 0, tot = 0;
#pragma unroll
        for (int cc = 0; cc < NUM_CHIPS; cc++) {
            const int v = g_counts[cc * N_EXPERTS + tid];
            if (cc < c) off += v;
            tot += v;
        }
        s_choff[tid] = off;
        const int eb = tid - c * EPC;
        if (eb >= 0 && eb < EPC) s_tot[eb] = tot;
        if (c == 0) out_cnt[tid] = (float)tot;   /* counters section */
    }
    __syncthreads();

    /* ---- Phase B: filled rows (srcrow + metadata) ---- */
#pragma unroll
    for (int r = 0; r < 4; r++) {
        const int j = w * 128 + r * 32 + lane;
        const int e = er[r];
        const int row = e * MAX_TOK + s_choff[e] + woff[w * 33 + e] + lr[r];
        const int tok = j >> 2, kk = j & (TOP_K - 1);
        g_srcrow[row] = c * SEQ + tok;
        __nv_bfloat16 wb = __float2bfloat16(wts[c * NPC + j]);  /* RNE */
        const int bits = (int)__bfloat16_as_short(wb);          /* sext */
        float4* m = (float4*)(meta + (size_t)row * META_LEN);
        m[0] = make_float4((float)c, (float)tok, (float)kk, (float)e);
        m[1] = make_float4((float)bits, 0.f, 0.f, 0.f);
    }

    /* ---- Phase C: tail rows of my chip's experts -> -1 ---- */
#pragma unroll
    for (int i = 0; i < ROWS_PER_BLOCK / 1024; i++) {
        const int row = c * ROWS_PER_BLOCK + i * 1024 + tid;
        const int rr = row & (MAX_TOK - 1);
        if (rr < s_tot[(row >> 10) & (EPC - 1)]) continue;   /* filled */
        g_srcrow[row] = -1;
        float4* m = (float4*)(meta + (size_t)row * META_LEN);
        const float4 neg = make_float4(-1.f, -1.f, -1.f, -1.f);
        m[0] = neg; m[1] = neg;
    }
}

/* ------------------------------------------------------------------ */
/* Copy kernel: one 128-thread block per output row (best measured).
   srcrow loaded once per warp; filled row = 4 indep LDG chains + 4
   STGs per thread; zero row = stores only.                            */
__global__ void __launch_bounds__(COPY_THREADS) k_copy(const float4* __restrict__ x4,
                                                       float4* __restrict__ buf4) {
    const unsigned row = blockIdx.x;
    const unsigned t = threadIdx.x;
    const int s = __ldg(&g_srcrow[row]);
    float4* dst = buf4 + row * V4_PER_ROW + t;

    if (s >= 0) {
        const float4* src = x4 + (unsigned)s * V4_PER_ROW + t;
        float4 v0 = __ldg(&src[0 * COPY_THREADS]);
        float4 v1 = __ldg(&src[1 * COPY_THREADS]);
        float4 v2 = __ldg(&src[2 * COPY_THREADS]);
        float4 v3 = __ldg(&src[3 * COPY_THREADS]);
        dst[0 * COPY_THREADS] = v0;
        dst[1 * COPY_THREADS] = v1;
        dst[2 * COPY_THREADS] = v2;
        dst[3 * COPY_THREADS] = v3;
    } else {
        const float4 z = make_float4(0.f, 0.f, 0.f, 0.f);
        dst[0 * COPY_THREADS] = z;
        dst[1 * COPY_THREADS] = z;
        dst[2 * COPY_THREADS] = z;
        dst[3 * COPY_THREADS] = z;
    }
}

/* ------------------------------------------------------------------ */
extern "C" void kernel_launch(void* const* d_in, const int* in_sizes, int n_in,
                              void* d_out, int out_size) {
    const float* x   = (const float*)d_in[0];
    const float* w   = (const float*)d_in[1];
    const int*   idx = (const int*)d_in[2];

    float* out  = (float*)d_out;
    float* buf  = out;                                                   /* 32*1024*2048 */
    float* meta = out + (size_t)NROWS * HIDDEN;                          /* 32*1024*8    */
    float* cnt  = meta + (size_t)NROWS * META_LEN;                       /* 32           */

    k_plan<<<NUM_CHIPS, 1024>>>(idx, w, meta, cnt);
    k_copy<<<NROWS, COPY_THREADS>>>((const float4*)x, (float4*)buf);
}

// round 9
// speedup vs baseline: 1.1559x; 1.1559x over previous
#include <cuda_runtime.h>
#include <cuda_bf16.h>

#define NUM_CHIPS 4
#define N_EXPERTS 32
#define TOP_K 4
#define SEQ 1024
#define HIDDEN 2048
#define MAX_TOK 1024
#define META_LEN 8
#define NPC (SEQ * TOP_K)            /* 4096 assignments per chip  */
#define NA (NUM_CHIPS * NPC)         /* 16384 total assignments    */
#define NROWS (N_EXPERTS * MAX_TOK)  /* 32768 output rows          */

#define V4_PER_ROW (HIDDEN / 4)      /* 512 float4 per row  */
#define COPY_THREADS 128             /* one block per row; 4 float4/thread */

/* scratch — no allocations allowed */
__device__ int g_counts[NUM_CHIPS * N_EXPERTS];
__device__ int g_rank[NA];        /* assignment -> stable rank within chip+expert  */
__device__ int2 g_pack[NROWS];    /* row -> {src token row | -1, assignment id}    */

/* ------------------------------------------------------------------ */
/* Kernel 1: stable within-chip rank via warp intrinsics.
   One block per chip, 1024 threads; warp w owns assignments
   [w*128, w*128+128) in 4 rounds of 32 (lane order = flat order).      */
__global__ void __launch_bounds__(1024) k_rank(const int* __restrict__ indices) {
    __shared__ int wcount[32 * 33];   /* [warp][expert], 33-padded */
    __shared__ int woff[32 * 33];
    const int c = blockIdx.x;
    const int tid = threadIdx.x, w = tid >> 5, lane = tid & 31;

    for (int i = tid; i < 32 * 33; i += 1024) wcount[i] = 0;
    __syncthreads();

    int er[4], lr[4];
#pragma unroll
    for (int r = 0; r < 4; r++) {
        const int j = w * 128 + r * 32 + lane;          /* coalesced */
        const int e = indices[c * NPC + j];
        const unsigned mask = __match_any_sync(0xffffffffu, e);
        const int leader = __ffs(mask) - 1;
        const int prefix = __popc(mask & ((1u << lane) - 1u));
        int base = 0;
        if (lane == leader) base = atomicAdd(&wcount[w * 33 + e], __popc(mask));
        base = __shfl_sync(0xffffffffu, base, leader);
        er[r] = e; lr[r] = base + prefix;
    }
    __syncthreads();

    /* warp e scans wcount[*][e] across the 32 warps (lane = warp idx) */
    {
        const int e = w;
        const int val = wcount[lane * 33 + e];
        int incl = val;
#pragma unroll
        for (int d = 1; d < 32; d <<= 1) {
            int n = __shfl_up_sync(0xffffffffu, incl, d);
            if (lane >= d) incl += n;
        }
        woff[lane * 33 + e] = incl - val;
        if (lane == 31) g_counts[c * N_EXPERTS + e] = incl;
    }
    __syncthreads();

#pragma unroll
    for (int r = 0; r < 4; r++) {
        const int j = w * 128 + r * 32 + lane;
        g_rank[c * NPC + j] = woff[w * 33 + er[r]] + lr[r];
    }
}

/* ------------------------------------------------------------------ */
/* Kernel 2 (small): row -> {src, assignment} table + counters.
   Threads [0,16384): assignment role (filled rows).
   Threads [16384,49152): row role (tail rows -> {-1,-1}).             */
__global__ void __launch_bounds__(256) k_prep(const int* __restrict__ indices,
                                              float* __restrict__ out_cnt) {
    const int t = blockIdx.x * 256 + threadIdx.x;
    if (t < NA) {
        const int c = t >> 12, n = t & (NPC - 1);
        const int tok = n >> 2;
        const int e = indices[t];                        /* coalesced */
        int off = 0;
#pragma unroll
        for (int cc = 0; cc < NUM_CHIPS - 1; cc++)
            if (cc < c) off += g_counts[cc * N_EXPERTS + e];
        const int row = e * MAX_TOK + off + g_rank[t];
        g_pack[row] = make_int2(c * SEQ + tok, t);
        if (t < N_EXPERTS) {                             /* counters section */
            int tot = 0;
#pragma unroll
            for (int cc = 0; cc < NUM_CHIPS; cc++) tot += g_counts[cc * N_EXPERTS + t];
            out_cnt[t] = (float)tot;
        }
    } else {
        const int row = t - NA;
        if (row >= NROWS) return;
        const int e = row >> 10, r = row & (MAX_TOK - 1);
        int tot = 0;
#pragma unroll
        for (int cc = 0; cc < NUM_CHIPS; cc++) tot += g_counts[cc * N_EXPERTS + e];
        if (r < tot) return;                             /* filled above */
        g_pack[row] = make_int2(-1, -1);
    }
}

/* ------------------------------------------------------------------ */
/* Kernel 3: one 128-thread block per output row. Emits the row data
   AND its metadata (thread 0), so the plan phase never touches meta.
   Filled row: 4 indep LDG chains + 4 STGs/thread. Zero: stores only.  */
__global__ void __launch_bounds__(COPY_THREADS) k_copy(const float4* __restrict__ x4,
                                                       const float* __restrict__ wts,
                                                       float* __restrict__ meta,
                                                       float4* __restrict__ buf4) {
    const unsigned row = blockIdx.x;
    const unsigned t = threadIdx.x;
    const int2 p = __ldg(&g_pack[row]);                  /* broadcast */
    float4* dst = buf4 + row * V4_PER_ROW + t;

    if (p.x >= 0) {
        const float4* src = x4 + (unsigned)p.x * V4_PER_ROW + t;
        float4 v0 = __ldg(&src[0 * COPY_THREADS]);
        float4 v1 = __ldg(&src[1 * COPY_THREADS]);
        float4 v2 = __ldg(&src[2 * COPY_THREADS]);
        float4 v3 = __ldg(&src[3 * COPY_THREADS]);
        dst[0 * COPY_THREADS] = v0;
        dst[1 * COPY_THREADS] = v1;
        dst[2 * COPY_THREADS] = v2;
        dst[3 * COPY_THREADS] = v3;
        if (t == 0) {
            const int a = p.y;
            const int c = a >> 12, n = a & (NPC - 1);
            const int tok = n >> 2, kk = n & (TOP_K - 1);
            const int e = (int)(row >> 10);
            __nv_bfloat16 wb = __float2bfloat16(__ldg(&wts[a]));  /* RNE */
            const int bits = (int)__bfloat16_as_short(wb);        /* sext */
            float4* m = (float4*)(meta + (size_t)row * META_LEN);
            m[0] = make_float4((float)c, (float)tok, (float)kk, (float)e);
            m[1] = make_float4((float)bits, 0.f, 0.f, 0.f);
        }
    } else {
        const float4 z = make_float4(0.f, 0.f, 0.f, 0.f);
        dst[0 * COPY_THREADS] = z;
        dst[1 * COPY_THREADS] = z;
        dst[2 * COPY_THREADS] = z;
        dst[3 * COPY_THREADS] = z;
        if (t == 0) {
            float4* m = (float4*)(meta + (size_t)row * META_LEN);
            const float4 neg = make_float4(-1.f, -1.f, -1.f, -1.f);
            m[0] = neg; m[1] = neg;
        }
    }
}

/* ------------------------------------------------------------------ */
extern "C" void kernel_launch(void* const* d_in, const int* in_sizes, int n_in,
                              void* d_out, int out_size) {
    const float* x   = (const float*)d_in[0];
    const float* w   = (const float*)d_in[1];
    const int*   idx = (const int*)d_in[2];

    float* out  = (float*)d_out;
    float* buf  = out;                                                   /* 32*1024*2048 */
    float* meta = out + (size_t)NROWS * HIDDEN;                          /* 32*1024*8    */
    float* cnt  = meta + (size_t)NROWS * META_LEN;                       /* 32           */

    k_rank<<<NUM_CHIPS, 1024>>>(idx);
    k_prep<<<(NA + NROWS + 255) / 256, 256>>>(idx, cnt);
    k_copy<<<NROWS, COPY_THREADS>>>((const float4*)x, w, meta, (float4*)buf);
}

// round 10
// speedup vs baseline: 1.1606x; 1.0041x over previous
#include <cuda_runtime.h>
#include <cuda_bf16.h>

#define NUM_CHIPS 4
#define N_EXPERTS 32
#define TOP_K 4
#define SEQ 1024
#define HIDDEN 2048
#define MAX_TOK 1024
#define META_LEN 8
#define NPC (SEQ * TOP_K)            /* 4096 assignments per chip  */
#define NA (NUM_CHIPS * NPC)         /* 16384 total assignments    */
#define NROWS (N_EXPERTS * MAX_TOK)  /* 32768 output rows          */
#define NWARPS (NA / 32)             /* 512 global warps           */

#define V4_PER_ROW (HIDDEN / 4)      /* 512 float4 per row  */
#define COPY_THREADS 128             /* one block per row; 4 float4/thread */

/* scratch — no allocations allowed; every cell rewritten each run */
__device__ int g_wcnt[NWARPS * N_EXPERTS];   /* [gw][e] per-warp counts  */
__device__ int g_woff[NWARPS * N_EXPERTS];   /* [gw][e] global prefix    */
__device__ int g_total[N_EXPERTS];
__device__ unsigned char g_lrank[NA];        /* intra-warp stable rank   */
__device__ int2 g_pack[NROWS];               /* row -> {src | -1, asn}   */

/* ------------------------------------------------------------------ */
/* Kernel 1: per-warp counts + intra-warp stable rank. No smem, no
   atomics, no syncs — pure warp intrinsics, 64 blocks.                */
__global__ void __launch_bounds__(256) k_count(const int* __restrict__ indices) {
    const int t = blockIdx.x * 256 + threadIdx.x;
    const int lane = threadIdx.x & 31;
    const unsigned gw = (unsigned)t >> 5;
    const int e = indices[t];

    const unsigned mask = __match_any_sync(0xffffffffu, e);
    g_lrank[t] = (unsigned char)__popc(mask & ((1u << lane) - 1u));

    int cnt = 0;
#pragma unroll
    for (int b = 0; b < N_EXPERTS; b++) {
        const unsigned m = __ballot_sync(0xffffffffu, e == b);
        if (lane == b) cnt = __popc(m);
    }
    g_wcnt[gw * N_EXPERTS + lane] = cnt;     /* coalesced, zeros included */
}

/* ------------------------------------------------------------------ */
/* Kernel 2: one block per expert — exclusive scan of 512 warp counts.
   Global warp order is chip-major, so this single scan IS the full
   "chips in order, then (token,topk)" offset. Also totals + counters. */
__global__ void __launch_bounds__(128) k_scan(float* __restrict__ out_cnt) {
    const int e = blockIdx.x;
    const int t = threadIdx.x, lane = t & 31, w = t >> 5;
    __shared__ int wsum[4];

    int v[4]; int s = 0;
#pragma unroll
    for (int j = 0; j < 4; j++) { v[j] = g_wcnt[(t * 4 + j) * N_EXPERTS + e]; s += v[j]; }

    int incl = s;
#pragma unroll
    for (int d = 1; d < 32; d <<= 1) {
        const int n = __shfl_up_sync(0xffffffffu, incl, d);
        if (lane >= d) incl += n;
    }
    if (lane == 31) wsum[w] = incl;
    __syncthreads();

    int base = 0;
#pragma unroll
    for (int ww = 0; ww < 4; ww++) if (ww < w) base += wsum[ww];

    int excl = base + incl - s;
#pragma unroll
    for (int j = 0; j < 4; j++) { g_woff[(t * 4 + j) * N_EXPERTS + e] = excl; excl += v[j]; }

    if (t == 127) {
        const int tot = wsum[0] + wsum[1] + wsum[2] + wsum[3];
        g_total[e] = tot;
        out_cnt[e] = (float)tot;
    }
}

/* ------------------------------------------------------------------ */
/* Kernel 3: row -> {src, assignment} table (pure lookups).
   Threads [0,16384): filled rows. [16384,49152): tail rows -> {-1,-1}. */
__global__ void __launch_bounds__(256) k_prep(const int* __restrict__ indices) {
    const int t = blockIdx.x * 256 + threadIdx.x;
    if (t < NA) {
        const int c = t >> 12, n = t & (NPC - 1);
        const int tok = n >> 2;
        const int e = indices[t];                                /* L2-hot */
        const unsigned gw = (unsigned)t >> 5;
        const int row = e * MAX_TOK + g_woff[gw * N_EXPERTS + e] /* coalesced line */
                        + (int)g_lrank[t];
        g_pack[row] = make_int2(c * SEQ + tok, t);
    } else {
        const int row = t - NA;
        if (row >= NROWS) return;
        const int e = row >> 10, r = row & (MAX_TOK - 1);
        if (r < g_total[e]) return;                              /* filled above */
        g_pack[row] = make_int2(-1, -1);
    }
}

/* ------------------------------------------------------------------ */
/* Kernel 4: one 128-thread block per output row; emits row data AND
   its metadata (thread 0). Filled: 4 indep LDG chains + 4 STGs per
   thread. Zero: stores only. (Measured 50.5us, DRAM 70% — ceiling.)   */
__global__ void __launch_bounds__(COPY_THREADS) k_copy(const float4* __restrict__ x4,
                                                       const float* __restrict__ wts,
                                                       float* __restrict__ meta,
                                                       float4* __restrict__ buf4) {
    const unsigned row = blockIdx.x;
    const unsigned t = threadIdx.x;
    const int2 p = __ldg(&g_pack[row]);                  /* broadcast */
    float4* dst = buf4 + row * V4_PER_ROW + t;

    if (p.x >= 0) {
        const float4* src = x4 + (unsigned)p.x * V4_PER_ROW + t;
        float4 v0 = __ldg(&src[0 * COPY_THREADS]);
        float4 v1 = __ldg(&src[1 * COPY_THREADS]);
        float4 v2 = __ldg(&src[2 * COPY_THREADS]);
        float4 v3 = __ldg(&src[3 * COPY_THREADS]);
        dst[0 * COPY_THREADS] = v0;
        dst[1 * COPY_THREADS] = v1;
        dst[2 * COPY_THREADS] = v2;
        dst[3 * COPY_THREADS] = v3;
        if (t == 0) {
            const int a = p.y;
            const int c = a >> 12, n = a & (NPC - 1);
            const int tok = n >> 2, kk = n & (TOP_K - 1);
            const int e = (int)(row >> 10);
            __nv_bfloat16 wb = __float2bfloat16(__ldg(&wts[a]));  /* RNE */
            const int bits = (int)__bfloat16_as_short(wb);        /* sext */
            float4* m = (float4*)(meta + (size_t)row * META_LEN);
            m[0] = make_float4((float)c, (float)tok, (float)kk, (float)e);
            m[1] = make_float4((float)bits, 0.f, 0.f, 0.f);
        }
    } else {
        const float4 z = make_float4(0.f, 0.f, 0.f, 0.f);
        dst[0 * COPY_THREADS] = z;
        dst[1 * COPY_THREADS] = z;
        dst[2 * COPY_THREADS] = z;
        dst[3 * COPY_THREADS] = z;
        if (t == 0) {
            float4* m = (float4*)(meta + (size_t)row * META_LEN);
            const float4 neg = make_float4(-1.f, -1.f, -1.f, -1.f);
            m[0] = neg; m[1] = neg;
        }
    }
}

/* ------------------------------------------------------------------ */
extern "C" void kernel_launch(void* const* d_in, const int* in_sizes, int n_in,
                              void* d_out, int out_size) {
    const float* x   = (const float*)d_in[0];
    const float* w   = (const float*)d_in[1];
    const int*   idx = (const int*)d_in[2];

    float* out  = (float*)d_out;
    float* buf  = out;                                                   /* 32*1024*2048 */
    float* meta = out + (size_t)NROWS * HIDDEN;                          /* 32*1024*8    */
    float* cnt  = meta + (size_t)NROWS * META_LEN;                       /* 32           */

    k_count<<<NA / 256, 256>>>(idx);
    k_scan<<<N_EXPERTS, 128>>>(cnt);
    k_prep<<<(NA + NROWS + 255) / 256, 256>>>(idx);
    k_copy<<<NROWS, COPY_THREADS>>>((const float4*)x, w, meta, (float4*)buf);
}